// round 1
// baseline (speedup 1.0000x reference)
#include <cuda_runtime.h>
#include <math.h>

#define NN 100000
#define EE 800000
#define ENN (EE + NN)

// ---------------- device scratch pools (no allocations allowed) -------------
static __device__ float g_fpool[460000000];   // ~1.84 GB
static __device__ int   g_ipool[2400000];

#define SZ_NF   ((size_t)NN * 128)
#define OFF_X0   ((size_t)0)                       // 2*SZ_NF  (x0 l,r)
#define OFF_XS   (OFF_X0 + 2 * SZ_NF)              // 6*SZ_NF  (xs[b][l])
#define OFF_MEAN (OFF_XS + 6 * SZ_NF)              // SZ_NF
#define OFF_XH   (OFF_MEAN + SZ_NF)                // NN*256
#define OFF_AS   (OFF_XH + (size_t)NN * 256)       // NN*2
#define OFF_AD   (OFF_AS + (size_t)NN * 2)         // NN*2
#define OFF_G    (OFF_AD + (size_t)NN * 2)         // NN*768
#define OFF_HF   (OFF_G + (size_t)NN * 768)        // 3*NN*192
#define OFF_HB   (OFF_HF + (size_t)3 * NN * 192)   // 3*NN*192
#define OFF_CST  (OFF_HB + (size_t)3 * NN * 192)   // NN*192
#define OFF_JK   (OFF_CST + (size_t)NN * 192)      // 2*SZ_NF
#define OFF_SQ   (OFF_JK + 2 * SZ_NF)              // 2*SZ_NF
#define OFF_O4   (OFF_SQ + 2 * SZ_NF)              // 4*SZ_NF
#define OFF_WIHT (OFF_O4 + 4 * SZ_NF)              // 4*128*768
#define OFF_WHHT (OFF_WIHT + (size_t)4 * 98304)    // 4*192*768
#define OFF_BSUM (OFF_WHHT + (size_t)4 * 147456)   // 4*768

#define IOFF_PTR 0                                 // 2*(NN+1)
#define IOFF_CUR (2 * (NN + 1))                    // 2*NN
#define IOFF_COL (IOFF_CUR + 2 * NN)               // 2*ENN

// ---------------- small helpers --------------------------------------------
__device__ __forceinline__ float warp_sum(float v) {
    #pragma unroll
    for (int o = 16; o; o >>= 1) v += __shfl_xor_sync(0xffffffffu, v, o);
    return v;
}
__device__ __forceinline__ float warp_max(float v) {
    #pragma unroll
    for (int o = 16; o; o >>= 1) v = fmaxf(v, __shfl_xor_sync(0xffffffffu, v, o));
    return v;
}
__device__ __forceinline__ float sigm(float x) { return 1.f / (1.f + expf(-x)); }

// ---------------- node feature build ----------------------------------------
__global__ void k_build_x(const int* __restrict__ x_idx, const float* __restrict__ x_flt,
                          const float* __restrict__ emb_aa, const float* __restrict__ emb_ss,
                          float* __restrict__ x0l, float* __restrict__ x0r) {
    int n = blockIdx.x, t = threadIdx.x;
    int ai = x_idx[2 * n], si = x_idx[2 * n + 1];
    float vl, vr;
    if (t < 123) {
        vl = emb_aa[(size_t)ai * 123 + t] + emb_ss[(size_t)si * 123 + t];
        vr = emb_aa[(size_t)(26 + ai) * 123 + t] + emb_ss[(size_t)(3 + si) * 123 + t];
    } else {
        float f = x_flt[(size_t)n * 5 + (t - 123)];
        vl = f; vr = f;
    }
    x0l[(size_t)n * 128 + t] = vl;
    x0r[(size_t)n * 128 + t] = vr;
}

// ---------------- CSR build --------------------------------------------------
__global__ void k_fill_int(int* p, int v, int n) {
    int i = blockIdx.x * blockDim.x + threadIdx.x;
    if (i < n) p[i] = v;
}
__global__ void k_hist(const int* __restrict__ dst, int* cnt, int E) {
    int e = blockIdx.x * blockDim.x + threadIdx.x;
    if (e < E) atomicAdd(&cnt[dst[e]], 1);
}
__global__ void k_scan(const int* __restrict__ cnt, int* __restrict__ indptr, int n) {
    __shared__ int sh[1024];
    __shared__ int carry_s;
    int t = threadIdx.x;
    if (t == 0) { carry_s = 0; indptr[0] = 0; }
    __syncthreads();
    for (int base = 0; base < n; base += 1024) {
        int i = base + t;
        int v = (i < n) ? cnt[i] : 0;
        sh[t] = v; __syncthreads();
        for (int off = 1; off < 1024; off <<= 1) {
            int add = (t >= off) ? sh[t - off] : 0;
            __syncthreads();
            sh[t] += add;
            __syncthreads();
        }
        if (i < n) indptr[i + 1] = carry_s + sh[t];
        __syncthreads();
        if (t == 0) carry_s += sh[1023];
        __syncthreads();
    }
}
__global__ void k_copy_int(const int* a, int* b, int n) {
    int i = blockIdx.x * blockDim.x + threadIdx.x;
    if (i < n) b[i] = a[i];
}
__global__ void k_scatter(const int* __restrict__ ei, int* cursor, int* colsrc, int E, int N) {
    int e = blockIdx.x * blockDim.x + threadIdx.x;
    if (e >= E + N) return;
    int s, d;
    if (e < E) { s = ei[e]; d = ei[E + e]; } else { s = e - E; d = s; }
    int pos = atomicAdd(&cursor[d], 1);
    colsrc[pos] = s;
}

// ---------------- weight transpose / bias sum --------------------------------
__global__ void k_transpose(const float* __restrict__ W, float* __restrict__ WT, int R, int C) {
    int idx = blockIdx.x * blockDim.x + threadIdx.x;
    if (idx >= R * C) return;
    int r = idx / C, c = idx - r * C;
    WT[(size_t)c * R + r] = W[idx];
}
__global__ void k_bsum(const float* __restrict__ a, const float* __restrict__ b, float* o, int n) {
    int i = blockIdx.x * blockDim.x + threadIdx.x;
    if (i < n) o[i] = a[i] + b[i];
}
__global__ void k_mean(const float* __restrict__ a, const float* __restrict__ b, float* o, size_t n) {
    size_t i = (size_t)blockIdx.x * blockDim.x + threadIdx.x;
    if (i < n) o[i] = 0.5f * (a[i] + b[i]);
}

// ---------------- SGEMM: C = A[MxK] @ B[KxN] (+bias) (+=C) -------------------
__global__ __launch_bounds__(256) void k_sgemm(
    const float* __restrict__ A, const float* __restrict__ B,
    const float* __restrict__ bias, float* __restrict__ C,
    int M, int Nc, int K, int doAcc) {
    __shared__ float As[16][128];
    __shared__ float Bs[16][128];
    const int bm = blockIdx.x * 128;
    const int bn = blockIdx.y * 128;
    const int tid = threadIdx.x;
    const int tx = tid & 15;
    const int ty = tid >> 4;
    float acc[8][8];
    #pragma unroll
    for (int i = 0; i < 8; i++)
        #pragma unroll
        for (int j = 0; j < 8; j++) acc[i][j] = 0.f;

    const int arow = tid >> 1;
    const int acol = (tid & 1) * 4;
    const int brow = tid >> 5;
    const int bcol = (tid & 31) * 4;
    const int gr = bm + arow;

    for (int k0 = 0; k0 < K; k0 += 16) {
        #pragma unroll
        for (int h = 0; h < 2; h++) {
            int ka = k0 + acol + h * 8;
            float4 av = make_float4(0.f, 0.f, 0.f, 0.f);
            if (gr < M) av = *(const float4*)(A + (size_t)gr * K + ka);
            As[acol + h * 8 + 0][arow] = av.x;
            As[acol + h * 8 + 1][arow] = av.y;
            As[acol + h * 8 + 2][arow] = av.z;
            As[acol + h * 8 + 3][arow] = av.w;
            int kb = k0 + brow + h * 8;
            float4 bv = *(const float4*)(B + (size_t)kb * Nc + bn + bcol);
            *(float4*)&Bs[brow + h * 8][bcol] = bv;
        }
        __syncthreads();
        #pragma unroll
        for (int kk = 0; kk < 16; kk++) {
            float ar[8], br[8];
            *(float4*)ar       = *(float4*)&As[kk][ty * 8];
            *(float4*)(ar + 4) = *(float4*)&As[kk][ty * 8 + 4];
            *(float4*)br       = *(float4*)&Bs[kk][tx * 8];
            *(float4*)(br + 4) = *(float4*)&Bs[kk][tx * 8 + 4];
            #pragma unroll
            for (int i = 0; i < 8; i++)
                #pragma unroll
                for (int j = 0; j < 8; j++)
                    acc[i][j] += ar[i] * br[j];
        }
        __syncthreads();
    }
    #pragma unroll
    for (int i = 0; i < 8; i++) {
        int row = bm + ty * 8 + i;
        if (row >= M) continue;
        #pragma unroll
        for (int j = 0; j < 8; j += 4) {
            int col = bn + tx * 8 + j;
            float4 v = make_float4(acc[i][j], acc[i][j + 1], acc[i][j + 2], acc[i][j + 3]);
            if (bias) {
                v.x += bias[col]; v.y += bias[col + 1]; v.z += bias[col + 2]; v.w += bias[col + 3];
            }
            float* cp = C + (size_t)row * Nc + col;
            if (doAcc) {
                float4 o = *(float4*)cp;
                v.x += o.x; v.y += o.y; v.z += o.z; v.w += o.w;
            }
            *(float4*)cp = v;
        }
    }
}

// ---------------- GAT attention scores ---------------------------------------
__global__ void k_att(const float* __restrict__ xh, const float* __restrict__ asv,
                      const float* __restrict__ adv, float* __restrict__ asrc,
                      float* __restrict__ adst, int N) {
    int w = (blockIdx.x * blockDim.x + threadIdx.x) >> 5;
    int lane = threadIdx.x & 31;
    if (w >= N) return;
    const float* row = xh + (size_t)w * 256;
    float s0 = 0, d0 = 0, s1 = 0, d1 = 0;
    #pragma unroll
    for (int c = lane; c < 128; c += 32) {
        float v0 = row[c], v1 = row[128 + c];
        s0 += v0 * asv[c];       d0 += v0 * adv[c];
        s1 += v1 * asv[128 + c]; d1 += v1 * adv[128 + c];
    }
    s0 = warp_sum(s0); d0 = warp_sum(d0); s1 = warp_sum(s1); d1 = warp_sum(d1);
    if (lane == 0) {
        asrc[2 * w] = s0; asrc[2 * w + 1] = s1;
        adst[2 * w] = d0; adst[2 * w + 1] = d1;
    }
}

// ---------------- GAT segment softmax + aggregate (warp per dst node) --------
__global__ void k_aggr(const int* __restrict__ indptr, const int* __restrict__ colsrc,
                       const float* __restrict__ xh, const float* __restrict__ asrc,
                       const float* __restrict__ adst, const float* __restrict__ bias,
                       const float* __restrict__ meanb, float* __restrict__ out, int N) {
    int w = (blockIdx.x * blockDim.x + threadIdx.x) >> 5;
    int lane = threadIdx.x & 31;
    if (w >= N) return;
    int p0 = indptr[w], p1 = indptr[w + 1];
    float ad0 = adst[2 * w], ad1 = adst[2 * w + 1];

    float m0 = -1e30f, m1 = -1e30f;
    for (int j = p0 + lane; j < p1; j += 32) {
        int s = colsrc[j];
        float e0 = asrc[2 * s] + ad0;     e0 = e0 > 0.f ? e0 : 0.2f * e0;
        float e1 = asrc[2 * s + 1] + ad1; e1 = e1 > 0.f ? e1 : 0.2f * e1;
        m0 = fmaxf(m0, e0); m1 = fmaxf(m1, e1);
    }
    m0 = warp_max(m0); m1 = warp_max(m1);

    float z0 = 0.f, z1 = 0.f;
    for (int j = p0 + lane; j < p1; j += 32) {
        int s = colsrc[j];
        float e0 = asrc[2 * s] + ad0;     e0 = e0 > 0.f ? e0 : 0.2f * e0;
        float e1 = asrc[2 * s + 1] + ad1; e1 = e1 > 0.f ? e1 : 0.2f * e1;
        z0 += expf(e0 - m0); z1 += expf(e1 - m1);
    }
    z0 = warp_sum(z0) + 1e-16f; z1 = warp_sum(z1) + 1e-16f;
    float inv0 = 1.f / z0, inv1 = 1.f / z1;

    float acc[8];
    #pragma unroll
    for (int k = 0; k < 8; k++) acc[k] = 0.f;
    for (int j = p0; j < p1; j++) {
        int s = colsrc[j];
        float e0 = asrc[2 * s] + ad0;     e0 = e0 > 0.f ? e0 : 0.2f * e0;
        float e1 = asrc[2 * s + 1] + ad1; e1 = e1 > 0.f ? e1 : 0.2f * e1;
        float w0 = expf(e0 - m0) * inv0;
        float w1 = expf(e1 - m1) * inv1;
        const float* xr = xh + (size_t)s * 256;
        #pragma unroll
        for (int k = 0; k < 4; k++) {
            acc[k]     += w0 * xr[lane + 32 * k];
            acc[4 + k] += w1 * xr[128 + lane + 32 * k];
        }
    }
    #pragma unroll
    for (int k = 0; k < 4; k++) {
        int c = lane + 32 * k;
        float v = 0.5f * (acc[k] + acc[4 + k]) + bias[c];
        v = v > 0.f ? v : 0.f;
        out[(size_t)w * 128 + c] = v + meanb[(size_t)w * 128 + c];
    }
}

// ---------------- LSTM cell ---------------------------------------------------
__global__ void k_lstm(const float* __restrict__ G, const float* __restrict__ bsum,
                       const float* __restrict__ cprev, float* __restrict__ cout,
                       float* __restrict__ hout, int N) {
    int idx = blockIdx.x * blockDim.x + threadIdx.x;
    if (idx >= N * 192) return;
    int n = idx / 192, j = idx - n * 192;
    const float* g = G + (size_t)n * 768;
    float gi = g[j]       + bsum[j];
    float gf = g[192 + j] + bsum[192 + j];
    float gg = g[384 + j] + bsum[384 + j];
    float go = g[576 + j] + bsum[576 + j];
    float c0 = cprev ? cprev[idx] : 0.f;
    float c = sigm(gf) * c0 + sigm(gi) * tanhf(gg);
    cout[idx] = c;
    hout[idx] = sigm(go) * tanhf(c);
}

// ---------------- JK attention ------------------------------------------------
__global__ void k_jk(const float* __restrict__ hf, const float* __restrict__ hb,
                     const float* __restrict__ attw,
                     const float* __restrict__ xs0, const float* __restrict__ xs1,
                     const float* __restrict__ xs2, float* __restrict__ jk, int N) {
    int w = (blockIdx.x * blockDim.x + threadIdx.x) >> 5;
    int lane = threadIdx.x & 31;
    if (w >= N) return;
    float a[3];
    #pragma unroll
    for (int l = 0; l < 3; l++) {
        const float* hfl = hf + ((size_t)l * NN + w) * 192;
        const float* hbl = hb + ((size_t)l * NN + w) * 192;
        float s = 0.f;
        #pragma unroll
        for (int c = lane; c < 192; c += 32)
            s += hfl[c] * attw[c] + hbl[c] * attw[192 + c];
        a[l] = warp_sum(s);
    }
    float m = fmaxf(a[0], fmaxf(a[1], a[2]));
    float e0 = expf(a[0] - m), e1 = expf(a[1] - m), e2 = expf(a[2] - m);
    float inv = 1.f / (e0 + e1 + e2);
    e0 *= inv; e1 *= inv; e2 *= inv;
    #pragma unroll
    for (int k = 0; k < 4; k++) {
        size_t o = (size_t)w * 128 + lane + 32 * k;
        jk[o] = xs0[o] * e0 + xs1[o] * e1 + xs2[o] * e2;
    }
}

// ---------------- final 4-way attention fusion --------------------------------
__global__ void k_final(const float* __restrict__ outs, const float* __restrict__ lw,
                        float* __restrict__ out, int N) {
    int w = (blockIdx.x * blockDim.x + threadIdx.x) >> 5;
    int lane = threadIdx.x & 31;
    if (w >= N) return;
    float s[4];
    #pragma unroll
    for (int i = 0; i < 4; i++) {
        const float* p = outs + (size_t)i * SZ_NF + (size_t)w * 128;
        float t = 0.f;
        #pragma unroll
        for (int c = lane; c < 128; c += 32) t += p[c] * lw[c];
        s[i] = warp_sum(t);
    }
    float m = fmaxf(fmaxf(s[0], s[1]), fmaxf(s[2], s[3]));
    float e[4]; float z = 0.f;
    #pragma unroll
    for (int i = 0; i < 4; i++) { e[i] = expf(s[i] - m); z += e[i]; }
    float inv = 1.f / z;
    #pragma unroll
    for (int k = 0; k < 4; k++) {
        int c = lane + 32 * k;
        float v = 0.f;
        #pragma unroll
        for (int i = 0; i < 4; i++) v += e[i] * inv * outs[(size_t)i * SZ_NF + (size_t)w * 128 + c];
        out[(size_t)w * 128 + c] = v;
    }
}

// ---------------- host orchestration -----------------------------------------
static inline void sgemm(const float* A, const float* B, const float* bias, float* C,
                         int M, int Nc, int K, int acc) {
    dim3 g((M + 127) / 128, Nc / 128), b(256);
    k_sgemm<<<g, b>>>(A, B, bias, C, M, Nc, K, acc);
}

extern "C" void kernel_launch(void* const* d_in, const int* in_sizes, int n_in,
                              void* d_out, int out_size) {
    const int*   x_idx   = (const int*)d_in[0];
    const float* x_flt   = (const float*)d_in[1];
    const int*   ei_l    = (const int*)d_in[2];
    const int*   ei_r    = (const int*)d_in[3];
    const float* emb_aa  = (const float*)d_in[4];
    const float* emb_ss  = (const float*)d_in[5];
    const float* conv_W  = (const float*)d_in[6];
    const float* att_src = (const float*)d_in[7];
    const float* att_dst = (const float*)d_in[8];
    const float* conv_b  = (const float*)d_in[9];
    const float* Wih     = (const float*)d_in[10];
    const float* Whh     = (const float*)d_in[11];
    const float* bih     = (const float*)d_in[12];
    const float* bhh     = (const float*)d_in[13];
    const float* jkW     = (const float*)d_in[14];
    const float* dW      = (const float*)d_in[16];
    const float* dB      = (const float*)d_in[17];
    const float* fW      = (const float*)d_in[18];
    const float* fB      = (const float*)d_in[19];
    const float* lW      = (const float*)d_in[20];
    float* out = (float*)d_out;
    (void)in_sizes; (void)n_in; (void)out_size; (void)d_in;

    float* fp = nullptr; int* ip = nullptr;
    cudaGetSymbolAddress((void**)&fp, g_fpool);
    cudaGetSymbolAddress((void**)&ip, g_ipool);

    float* X0[2]  = { fp + OFF_X0, fp + OFF_X0 + SZ_NF };
    float* MEAN   = fp + OFF_MEAN;
    float* XH     = fp + OFF_XH;
    float* ASRC   = fp + OFF_AS;
    float* ADST   = fp + OFF_AD;
    float* G      = fp + OFF_G;
    float* HF     = fp + OFF_HF;
    float* HB     = fp + OFF_HB;
    float* CST    = fp + OFF_CST;
    float* JK[2]  = { fp + OFF_JK, fp + OFF_JK + SZ_NF };
    float* SQ[2]  = { fp + OFF_SQ, fp + OFF_SQ + SZ_NF };
    float* O4     = fp + OFF_O4;
    float* WIHT   = fp + OFF_WIHT;
    float* WHHT   = fp + OFF_WHHT;
    float* BSUM   = fp + OFF_BSUM;

    int* PTR[2] = { ip + IOFF_PTR, ip + IOFF_PTR + (NN + 1) };
    int* CUR[2] = { ip + IOFF_CUR, ip + IOFF_CUR + NN };
    int* COL[2] = { ip + IOFF_COL, ip + IOFF_COL + ENN };
    const int* EI[2] = { ei_l, ei_r };

    const int WB = 12500;   // blocks for warp-per-node kernels (8 warps/block)

    // node features
    k_build_x<<<NN, 128>>>(x_idx, x_flt, emb_aa, emb_ss, X0[0], X0[1]);

    // CSR per branch (dst-sorted, self-loops included)
    for (int b = 0; b < 2; b++) {
        k_fill_int<<<(NN + 255) / 256, 256>>>(CUR[b], 1, NN);
        k_hist<<<(EE + 255) / 256, 256>>>(EI[b] + EE, CUR[b], EE);
        k_scan<<<1, 1024>>>(CUR[b], PTR[b], NN);
        k_copy_int<<<(NN + 255) / 256, 256>>>(PTR[b], CUR[b], NN);
        k_scatter<<<(ENN + 255) / 256, 256>>>(EI[b], CUR[b], COL[b], EE, NN);
    }

    // transposed LSTM weights + combined biases
    for (int bd = 0; bd < 4; bd++) {
        k_transpose<<<(768 * 128 + 255) / 256, 256>>>(Wih + (size_t)bd * 768 * 128,
                                                      WIHT + (size_t)bd * 98304, 768, 128);
        k_transpose<<<(768 * 192 + 255) / 256, 256>>>(Whh + (size_t)bd * 768 * 192,
                                                      WHHT + (size_t)bd * 147456, 768, 192);
    }
    k_bsum<<<(3072 + 255) / 256, 256>>>(bih, bhh, BSUM, 3072);

    // GAT layers
    const float* xcur[2] = { X0[0], X0[1] };
    for (int i = 0; i < 3; i++) {
        k_mean<<<(int)((SZ_NF + 255) / 256), 256>>>(xcur[0], xcur[1], MEAN, SZ_NF);
        for (int b = 0; b < 2; b++) {
            float* xs_out = fp + OFF_XS + ((size_t)b * 3 + i) * SZ_NF;
            sgemm(xcur[b], conv_W + ((size_t)b * 3 + i) * 128 * 256, nullptr, XH,
                  NN, 256, 128, 0);
            k_att<<<WB, 256>>>(XH, att_src + ((size_t)b * 3 + i) * 256,
                               att_dst + ((size_t)b * 3 + i) * 256, ASRC, ADST, NN);
            k_aggr<<<WB, 256>>>(PTR[b], COL[b], XH, ASRC, ADST,
                                conv_b + ((size_t)b * 3 + i) * 128, MEAN, xs_out, NN);
        }
        xcur[0] = fp + OFF_XS + (size_t)i * SZ_NF;
        xcur[1] = fp + OFF_XS + ((size_t)3 + i) * SZ_NF;
    }

    // JK bi-LSTM + layer attention, per branch
    for (int b = 0; b < 2; b++) {
        for (int d = 0; d < 2; d++) {
            int bd = b * 2 + d;
            float* Hbuf = (d == 0) ? HF : HB;
            const float* hprev = nullptr;
            for (int step = 0; step < 3; step++) {
                int si = (d == 0) ? step : 2 - step;
                const float* xs = fp + OFF_XS + ((size_t)b * 3 + si) * SZ_NF;
                sgemm(xs, WIHT + (size_t)bd * 98304, nullptr, G, NN, 768, 128, 0);
                if (step > 0)
                    sgemm(hprev, WHHT + (size_t)bd * 147456, nullptr, G, NN, 768, 192, 1);
                float* hout = Hbuf + (size_t)si * NN * 192;
                k_lstm<<<(NN * 192 + 255) / 256, 256>>>(G, BSUM + (size_t)bd * 768,
                                                        (step == 0) ? nullptr : CST,
                                                        CST, hout, NN);
                hprev = hout;
            }
        }
        k_jk<<<WB, 256>>>(HF, HB, jkW + (size_t)b * 384,
                          fp + OFF_XS + ((size_t)b * 3 + 0) * SZ_NF,
                          fp + OFF_XS + ((size_t)b * 3 + 1) * SZ_NF,
                          fp + OFF_XS + ((size_t)b * 3 + 2) * SZ_NF, JK[b], NN);
    }

    // heads
    for (int b = 0; b < 2; b++)
        sgemm(JK[b], dW + (size_t)b * 128 * 128, dB + (size_t)b * 128, SQ[b],
              NN, 128, 128, 0);
    const float* feats[4] = { JK[0], SQ[0], JK[1], SQ[1] };
    for (int i = 0; i < 4; i++)
        sgemm(feats[i], fW + (size_t)i * 128 * 128, fB + (size_t)i * 128,
              O4 + (size_t)i * SZ_NF, NN, 128, 128, 0);

    k_final<<<WB, 256>>>(O4, lW, out, NN);
}

// round 4
// speedup vs baseline: 1.4366x; 1.4366x over previous
#include <cuda_runtime.h>
#include <math.h>
#include <stdint.h>

#define NN 100000
#define EE 800000
#define ENN (EE + NN)

// ---------------- device scratch pools (no allocations allowed) -------------
static __device__ float g_fpool[460000000];   // ~1.84 GB
static __device__ int   g_ipool[2400000];

#define SZ_NF   ((size_t)NN * 128)
#define OFF_X0   ((size_t)0)                       // 2*SZ_NF  (x0 l,r)
#define OFF_XS   (OFF_X0 + 2 * SZ_NF)              // 6*SZ_NF  (xs[b][l])
#define OFF_MEAN (OFF_XS + 6 * SZ_NF)              // SZ_NF
#define OFF_XH   (OFF_MEAN + SZ_NF)                // NN*256
#define OFF_AS   (OFF_XH + (size_t)NN * 256)       // NN*2
#define OFF_AD   (OFF_AS + (size_t)NN * 2)         // NN*2
#define OFF_G    (OFF_AD + (size_t)NN * 2)         // NN*768
#define OFF_HF   (OFF_G + (size_t)NN * 768)        // 3*NN*192
#define OFF_HB   (OFF_HF + (size_t)3 * NN * 192)   // 3*NN*192
#define OFF_CST  (OFF_HB + (size_t)3 * NN * 192)   // NN*192
#define OFF_JK   (OFF_CST + (size_t)NN * 192)      // 2*SZ_NF
#define OFF_SQ   (OFF_JK + 2 * SZ_NF)              // 2*SZ_NF
#define OFF_O4   (OFF_SQ + 2 * SZ_NF)              // 4*SZ_NF
#define OFF_WIHT (OFF_O4 + 4 * SZ_NF)              // 4*128*768
#define OFF_WHHT (OFF_WIHT + (size_t)4 * 98304)    // 4*192*768
#define OFF_BSUM (OFF_WHHT + (size_t)4 * 147456)   // 4*768

#define IOFF_PTR 0                                 // 2*(NN+1)
#define IOFF_CUR (2 * (NN + 1))                    // 2*NN
#define IOFF_COL (IOFF_CUR + 2 * NN)               // 2*ENN

// ---------------- small helpers --------------------------------------------
__device__ __forceinline__ float warp_sum(float v) {
    #pragma unroll
    for (int o = 16; o; o >>= 1) v += __shfl_xor_sync(0xffffffffu, v, o);
    return v;
}
__device__ __forceinline__ float warp_max(float v) {
    #pragma unroll
    for (int o = 16; o; o >>= 1) v = fmaxf(v, __shfl_xor_sync(0xffffffffu, v, o));
    return v;
}
__device__ __forceinline__ float sigm(float x) { return 1.f / (1.f + expf(-x)); }

__device__ __forceinline__ uint32_t f2tf(float x) {
    uint32_t r;
    asm("cvt.rna.tf32.f32 %0, %1;" : "=r"(r) : "f"(x));
    return r;
}
__device__ __forceinline__ void mma8(float* c, const uint32_t* a, uint32_t b0, uint32_t b1) {
    asm volatile("mma.sync.aligned.m16n8k8.row.col.f32.tf32.tf32.f32 "
                 "{%0,%1,%2,%3},{%4,%5,%6,%7},{%8,%9},{%0,%1,%2,%3};"
                 : "+f"(c[0]), "+f"(c[1]), "+f"(c[2]), "+f"(c[3])
                 : "r"(a[0]), "r"(a[1]), "r"(a[2]), "r"(a[3]), "r"(b0), "r"(b1));
}

// ---------------- node feature build ----------------------------------------
__global__ void k_build_x(const int* __restrict__ x_idx, const float* __restrict__ x_flt,
                          const float* __restrict__ emb_aa, const float* __restrict__ emb_ss,
                          float* __restrict__ x0l, float* __restrict__ x0r) {
    int n = blockIdx.x, t = threadIdx.x;
    int ai = x_idx[2 * n], si = x_idx[2 * n + 1];
    float vl, vr;
    if (t < 123) {
        vl = emb_aa[(size_t)ai * 123 + t] + emb_ss[(size_t)si * 123 + t];
        vr = emb_aa[(size_t)(26 + ai) * 123 + t] + emb_ss[(size_t)(3 + si) * 123 + t];
    } else {
        float f = x_flt[(size_t)n * 5 + (t - 123)];
        vl = f; vr = f;
    }
    x0l[(size_t)n * 128 + t] = vl;
    x0r[(size_t)n * 128 + t] = vr;
}

// ---------------- CSR build --------------------------------------------------
__global__ void k_fill_int(int* p, int v, int n) {
    int i = blockIdx.x * blockDim.x + threadIdx.x;
    if (i < n) p[i] = v;
}
__global__ void k_hist(const int* __restrict__ dst, int* cnt, int E) {
    int e = blockIdx.x * blockDim.x + threadIdx.x;
    if (e < E) atomicAdd(&cnt[dst[e]], 1);
}
// chunked scan: one block, each thread owns a contiguous chunk
__global__ void k_scan(const int* __restrict__ cnt, int* __restrict__ indptr, int n) {
    __shared__ int sh[1024];
    int t = threadIdx.x;
    int chunk = (n + 1023) >> 10;
    int s0 = t * chunk;
    int s1 = s0 + chunk; if (s1 > n) s1 = n;
    int sum = 0;
    for (int i = s0; i < s1; i++) sum += cnt[i];
    sh[t] = sum;
    __syncthreads();
    for (int off = 1; off < 1024; off <<= 1) {
        int v = (t >= off) ? sh[t - off] : 0;
        __syncthreads();
        sh[t] += v;
        __syncthreads();
    }
    int run = (t == 0) ? 0 : sh[t - 1];
    if (t == 0) indptr[0] = 0;
    for (int i = s0; i < s1; i++) { run += cnt[i]; indptr[i + 1] = run; }
}
__global__ void k_copy_int(const int* a, int* b, int n) {
    int i = blockIdx.x * blockDim.x + threadIdx.x;
    if (i < n) b[i] = a[i];
}
__global__ void k_scatter(const int* __restrict__ ei, int* cursor, int* colsrc, int E, int N) {
    int e = blockIdx.x * blockDim.x + threadIdx.x;
    if (e >= E + N) return;
    int s, d;
    if (e < E) { s = ei[e]; d = ei[E + e]; } else { s = e - E; d = s; }
    int pos = atomicAdd(&cursor[d], 1);
    colsrc[pos] = s;
}

// ---------------- weight transpose / bias sum --------------------------------
__global__ void k_transpose(const float* __restrict__ W, float* __restrict__ WT, int R, int C) {
    int idx = blockIdx.x * blockDim.x + threadIdx.x;
    if (idx >= R * C) return;
    int r = idx / C, c = idx - r * C;
    WT[(size_t)c * R + r] = W[idx];
}
__global__ void k_bsum(const float* __restrict__ a, const float* __restrict__ b, float* o, int n) {
    int i = blockIdx.x * blockDim.x + threadIdx.x;
    if (i < n) o[i] = a[i] + b[i];
}
__global__ void k_mean(const float* __restrict__ a, const float* __restrict__ b, float* o, size_t n) {
    size_t i = (size_t)blockIdx.x * blockDim.x + threadIdx.x;
    if (i < n) o[i] = 0.5f * (a[i] + b[i]);
}

// ---------------- TF32 tensor-core GEMM: C = A[MxK] @ B[KxN] -----------------
// SPLIT=1: hi/lo split-tf32 (3 MMAs) for ~fp32 accuracy.
// Block 128x128, BK=16, 8 warps (2x4), warp tile 64x32 of m16n8k8.
template<int SPLIT>
__global__ __launch_bounds__(256) void k_gemm_tf32(
    const float* __restrict__ A, const float* __restrict__ B,
    const float* __restrict__ bias, float* __restrict__ C,
    int M, int Nc, int K, int doAcc) {
    __shared__ uint32_t Ash[16][136];
    __shared__ uint32_t Bsh[16][136];
    __shared__ uint32_t Asl[SPLIT ? 16 : 1][SPLIT ? 136 : 1];
    __shared__ uint32_t Bsl[SPLIT ? 16 : 1][SPLIT ? 136 : 1];

    const int bm = blockIdx.x * 128, bn = blockIdx.y * 128;
    const int tid = threadIdx.x, lane = tid & 31, w = tid >> 5;
    const int wm = (w & 1) * 64, wn = (w >> 1) * 32;
    const int gid = lane >> 2, t4 = lane & 3;

    float acc[4][4][4];
    #pragma unroll
    for (int i = 0; i < 4; i++)
        #pragma unroll
        for (int j = 0; j < 4; j++)
            #pragma unroll
            for (int r = 0; r < 4; r++) acc[i][j][r] = 0.f;

    const int arow = tid >> 1, akb = (tid & 1) * 8;
    const int brow = tid >> 4, bcol = (tid & 15) * 8;
    const bool arow_ok = (bm + arow) < M;

    for (int k0 = 0; k0 < K; k0 += 16) {
        // A tile (transposed to [k][m])
        #pragma unroll
        for (int h = 0; h < 2; h++) {
            float vv[4] = {0.f, 0.f, 0.f, 0.f};
            if (arow_ok)
                *(float4*)vv = *(const float4*)(A + (size_t)(bm + arow) * K + k0 + akb + h * 4);
            #pragma unroll
            for (int j = 0; j < 4; j++) {
                uint32_t hi = f2tf(vv[j]);
                Ash[akb + h * 4 + j][arow] = hi;
                if (SPLIT) Asl[akb + h * 4 + j][arow] = f2tf(vv[j] - __uint_as_float(hi));
            }
        }
        // B tile ([k][n])
        #pragma unroll
        for (int h = 0; h < 2; h++) {
            float vv[4];
            *(float4*)vv = *(const float4*)(B + (size_t)(k0 + brow) * Nc + bn + bcol + h * 4);
            uint32_t hh[4], ll[4];
            #pragma unroll
            for (int j = 0; j < 4; j++) {
                hh[j] = f2tf(vv[j]);
                if (SPLIT) ll[j] = f2tf(vv[j] - __uint_as_float(hh[j]));
            }
            *(uint4*)&Bsh[brow][bcol + h * 4] = *(uint4*)hh;
            if (SPLIT) *(uint4*)&Bsl[brow][bcol + h * 4] = *(uint4*)ll;
        }
        __syncthreads();

        #pragma unroll
        for (int ks = 0; ks < 16; ks += 8) {
            uint32_t ah[4][4], al[SPLIT ? 4 : 1][SPLIT ? 4 : 1];
            #pragma unroll
            for (int mt = 0; mt < 4; mt++) {
                int m = wm + mt * 16 + gid;
                ah[mt][0] = Ash[ks + t4][m];
                ah[mt][1] = Ash[ks + t4][m + 8];
                ah[mt][2] = Ash[ks + t4 + 4][m];
                ah[mt][3] = Ash[ks + t4 + 4][m + 8];
                if (SPLIT) {
                    al[mt][0] = Asl[ks + t4][m];
                    al[mt][1] = Asl[ks + t4][m + 8];
                    al[mt][2] = Asl[ks + t4 + 4][m];
                    al[mt][3] = Asl[ks + t4 + 4][m + 8];
                }
            }
            #pragma unroll
            for (int nt = 0; nt < 4; nt++) {
                int nn = wn + nt * 8 + gid;
                uint32_t b0 = Bsh[ks + t4][nn];
                uint32_t b1 = Bsh[ks + t4 + 4][nn];
                uint32_t b0l = 0, b1l = 0;
                if (SPLIT) { b0l = Bsl[ks + t4][nn]; b1l = Bsl[ks + t4 + 4][nn]; }
                #pragma unroll
                for (int mt = 0; mt < 4; mt++) {
                    mma8(acc[mt][nt], ah[mt], b0, b1);
                    if (SPLIT) {
                        mma8(acc[mt][nt], ah[mt], b0l, b1l);
                        mma8(acc[mt][nt], al[mt], b0, b1);
                    }
                }
            }
        }
        __syncthreads();
    }

    // epilogue
    #pragma unroll
    for (int mt = 0; mt < 4; mt++) {
        int r0 = bm + wm + mt * 16 + gid;
        #pragma unroll
        for (int nt = 0; nt < 4; nt++) {
            int c = bn + wn + nt * 8 + 2 * t4;
            float bx = 0.f, by = 0.f;
            if (bias) { bx = bias[c]; by = bias[c + 1]; }
            if (r0 < M) {
                float* p = C + (size_t)r0 * Nc + c;
                float2 v = make_float2(acc[mt][nt][0] + bx, acc[mt][nt][1] + by);
                if (doAcc) { float2 o = *(float2*)p; v.x += o.x; v.y += o.y; }
                *(float2*)p = v;
            }
            if (r0 + 8 < M) {
                float* p = C + (size_t)(r0 + 8) * Nc + c;
                float2 v = make_float2(acc[mt][nt][2] + bx, acc[mt][nt][3] + by);
                if (doAcc) { float2 o = *(float2*)p; v.x += o.x; v.y += o.y; }
                *(float2*)p = v;
            }
        }
    }
}

// ---------------- GAT attention scores ---------------------------------------
__global__ void k_att(const float* __restrict__ xh, const float* __restrict__ asv,
                      const float* __restrict__ adv, float* __restrict__ asrc,
                      float* __restrict__ adst, int N) {
    int w = (blockIdx.x * blockDim.x + threadIdx.x) >> 5;
    int lane = threadIdx.x & 31;
    if (w >= N) return;
    const float* row = xh + (size_t)w * 256;
    float s0 = 0, d0 = 0, s1 = 0, d1 = 0;
    #pragma unroll
    for (int c = lane; c < 128; c += 32) {
        float v0 = row[c], v1 = row[128 + c];
        s0 += v0 * asv[c];       d0 += v0 * adv[c];
        s1 += v1 * asv[128 + c]; d1 += v1 * adv[128 + c];
    }
    s0 = warp_sum(s0); d0 = warp_sum(d0); s1 = warp_sum(s1); d1 = warp_sum(d1);
    if (lane == 0) {
        asrc[2 * w] = s0; asrc[2 * w + 1] = s1;
        adst[2 * w] = d0; adst[2 * w + 1] = d1;
    }
}

// ---------------- GAT segment softmax + aggregate (warp per dst node) --------
__global__ void k_aggr(const int* __restrict__ indptr, const int* __restrict__ colsrc,
                       const float* __restrict__ xh, const float* __restrict__ asrc,
                       const float* __restrict__ adst, const float* __restrict__ bias,
                       const float* __restrict__ meanb, float* __restrict__ out, int N) {
    int w = (blockIdx.x * blockDim.x + threadIdx.x) >> 5;
    int lane = threadIdx.x & 31;
    if (w >= N) return;
    int p0 = indptr[w], p1 = indptr[w + 1];
    float ad0 = adst[2 * w], ad1 = adst[2 * w + 1];

    float m0 = -1e30f, m1 = -1e30f;
    for (int j = p0 + lane; j < p1; j += 32) {
        int s = colsrc[j];
        float e0 = asrc[2 * s] + ad0;     e0 = e0 > 0.f ? e0 : 0.2f * e0;
        float e1 = asrc[2 * s + 1] + ad1; e1 = e1 > 0.f ? e1 : 0.2f * e1;
        m0 = fmaxf(m0, e0); m1 = fmaxf(m1, e1);
    }
    m0 = warp_max(m0); m1 = warp_max(m1);

    float z0 = 0.f, z1 = 0.f;
    for (int j = p0 + lane; j < p1; j += 32) {
        int s = colsrc[j];
        float e0 = asrc[2 * s] + ad0;     e0 = e0 > 0.f ? e0 : 0.2f * e0;
        float e1 = asrc[2 * s + 1] + ad1; e1 = e1 > 0.f ? e1 : 0.2f * e1;
        z0 += expf(e0 - m0); z1 += expf(e1 - m1);
    }
    z0 = warp_sum(z0) + 1e-16f; z1 = warp_sum(z1) + 1e-16f;
    float inv0 = 1.f / z0, inv1 = 1.f / z1;

    float acc[8];
    #pragma unroll
    for (int k = 0; k < 8; k++) acc[k] = 0.f;
    for (int j = p0; j < p1; j++) {
        int s = colsrc[j];
        float e0 = asrc[2 * s] + ad0;     e0 = e0 > 0.f ? e0 : 0.2f * e0;
        float e1 = asrc[2 * s + 1] + ad1; e1 = e1 > 0.f ? e1 : 0.2f * e1;
        float w0 = expf(e0 - m0) * inv0;
        float w1 = expf(e1 - m1) * inv1;
        const float* xr = xh + (size_t)s * 256;
        #pragma unroll
        for (int k = 0; k < 4; k++) {
            acc[k]     += w0 * xr[lane + 32 * k];
            acc[4 + k] += w1 * xr[128 + lane + 32 * k];
        }
    }
    #pragma unroll
    for (int k = 0; k < 4; k++) {
        int c = lane + 32 * k;
        float v = 0.5f * (acc[k] + acc[4 + k]) + bias[c];
        v = v > 0.f ? v : 0.f;
        out[(size_t)w * 128 + c] = v + meanb[(size_t)w * 128 + c];
    }
}

// ---------------- LSTM cell ---------------------------------------------------
__global__ void k_lstm(const float* __restrict__ G, const float* __restrict__ bsum,
                       const float* __restrict__ cprev, float* __restrict__ cout,
                       float* __restrict__ hout, int N) {
    int idx = blockIdx.x * blockDim.x + threadIdx.x;
    if (idx >= N * 192) return;
    int n = idx / 192, j = idx - n * 192;
    const float* g = G + (size_t)n * 768;
    float gi = g[j]       + bsum[j];
    float gf = g[192 + j] + bsum[192 + j];
    float gg = g[384 + j] + bsum[384 + j];
    float go = g[576 + j] + bsum[576 + j];
    float c0 = cprev ? cprev[idx] : 0.f;
    float c = sigm(gf) * c0 + sigm(gi) * tanhf(gg);
    cout[idx] = c;
    hout[idx] = sigm(go) * tanhf(c);
}

// ---------------- JK attention ------------------------------------------------
__global__ void k_jk(const float* __restrict__ hf, const float* __restrict__ hb,
                     const float* __restrict__ attw,
                     const float* __restrict__ xs0, const float* __restrict__ xs1,
                     const float* __restrict__ xs2, float* __restrict__ jk, int N) {
    int w = (blockIdx.x * blockDim.x + threadIdx.x) >> 5;
    int lane = threadIdx.x & 31;
    if (w >= N) return;
    float a[3];
    #pragma unroll
    for (int l = 0; l < 3; l++) {
        const float* hfl = hf + ((size_t)l * NN + w) * 192;
        const float* hbl = hb + ((size_t)l * NN + w) * 192;
        float s = 0.f;
        #pragma unroll
        for (int c = lane; c < 192; c += 32)
            s += hfl[c] * attw[c] + hbl[c] * attw[192 + c];
        a[l] = warp_sum(s);
    }
    float m = fmaxf(a[0], fmaxf(a[1], a[2]));
    float e0 = expf(a[0] - m), e1 = expf(a[1] - m), e2 = expf(a[2] - m);
    float inv = 1.f / (e0 + e1 + e2);
    e0 *= inv; e1 *= inv; e2 *= inv;
    #pragma unroll
    for (int k = 0; k < 4; k++) {
        size_t o = (size_t)w * 128 + lane + 32 * k;
        jk[o] = xs0[o] * e0 + xs1[o] * e1 + xs2[o] * e2;
    }
}

// ---------------- final 4-way attention fusion --------------------------------
__global__ void k_final(const float* __restrict__ outs, const float* __restrict__ lw,
                        float* __restrict__ out, int N) {
    int w = (blockIdx.x * blockDim.x + threadIdx.x) >> 5;
    int lane = threadIdx.x & 31;
    if (w >= N) return;
    float s[4];
    #pragma unroll
    for (int i = 0; i < 4; i++) {
        const float* p = outs + (size_t)i * SZ_NF + (size_t)w * 128;
        float t = 0.f;
        #pragma unroll
        for (int c = lane; c < 128; c += 32) t += p[c] * lw[c];
        s[i] = warp_sum(t);
    }
    float m = fmaxf(fmaxf(s[0], s[1]), fmaxf(s[2], s[3]));
    float e[4]; float z = 0.f;
    #pragma unroll
    for (int i = 0; i < 4; i++) { e[i] = expf(s[i] - m); z += e[i]; }
    float inv = 1.f / z;
    #pragma unroll
    for (int k = 0; k < 4; k++) {
        int c = lane + 32 * k;
        float v = 0.f;
        #pragma unroll
        for (int i = 0; i < 4; i++) v += e[i] * inv * outs[(size_t)i * SZ_NF + (size_t)w * 128 + c];
        out[(size_t)w * 128 + c] = v;
    }
}

// ---------------- host orchestration -----------------------------------------
static inline void gemm(const float* A, const float* B, const float* bias, float* C,
                        int M, int Nc, int K, int acc, int split) {
    dim3 g((M + 127) / 128, Nc / 128), b(256);
    if (split) k_gemm_tf32<1><<<g, b>>>(A, B, bias, C, M, Nc, K, acc);
    else       k_gemm_tf32<0><<<g, b>>>(A, B, bias, C, M, Nc, K, acc);
}

extern "C" void kernel_launch(void* const* d_in, const int* in_sizes, int n_in,
                              void* d_out, int out_size) {
    const int*   x_idx   = (const int*)d_in[0];
    const float* x_flt   = (const float*)d_in[1];
    const int*   ei_l    = (const int*)d_in[2];
    const int*   ei_r    = (const int*)d_in[3];
    const float* emb_aa  = (const float*)d_in[4];
    const float* emb_ss  = (const float*)d_in[5];
    const float* conv_W  = (const float*)d_in[6];
    const float* att_src = (const float*)d_in[7];
    const float* att_dst = (const float*)d_in[8];
    const float* conv_b  = (const float*)d_in[9];
    const float* Wih     = (const float*)d_in[10];
    const float* Whh     = (const float*)d_in[11];
    const float* bih     = (const float*)d_in[12];
    const float* bhh     = (const float*)d_in[13];
    const float* jkW     = (const float*)d_in[14];
    const float* dW      = (const float*)d_in[16];
    const float* dB      = (const float*)d_in[17];
    const float* fW      = (const float*)d_in[18];
    const float* fB      = (const float*)d_in[19];
    const float* lW      = (const float*)d_in[20];
    float* out = (float*)d_out;
    (void)in_sizes; (void)n_in; (void)out_size;

    float* fp = nullptr; int* ip = nullptr;
    cudaGetSymbolAddress((void**)&fp, g_fpool);
    cudaGetSymbolAddress((void**)&ip, g_ipool);

    float* X0[2]  = { fp + OFF_X0, fp + OFF_X0 + SZ_NF };
    float* MEAN   = fp + OFF_MEAN;
    float* XH     = fp + OFF_XH;
    float* ASRC   = fp + OFF_AS;
    float* ADST   = fp + OFF_AD;
    float* G      = fp + OFF_G;
    float* HF     = fp + OFF_HF;
    float* HB     = fp + OFF_HB;
    float* CST    = fp + OFF_CST;
    float* JK[2]  = { fp + OFF_JK, fp + OFF_JK + SZ_NF };
    float* SQ[2]  = { fp + OFF_SQ, fp + OFF_SQ + SZ_NF };
    float* O4     = fp + OFF_O4;
    float* WIHT   = fp + OFF_WIHT;
    float* WHHT   = fp + OFF_WHHT;
    float* BSUM   = fp + OFF_BSUM;

    int* PTR[2] = { ip + IOFF_PTR, ip + IOFF_PTR + (NN + 1) };
    int* CUR[2] = { ip + IOFF_CUR, ip + IOFF_CUR + NN };
    int* COL[2] = { ip + IOFF_COL, ip + IOFF_COL + ENN };
    const int* EI[2] = { ei_l, ei_r };

    const int WB = 12500;   // blocks for warp-per-node kernels (8 warps/block)

    // node features
    k_build_x<<<NN, 128>>>(x_idx, x_flt, emb_aa, emb_ss, X0[0], X0[1]);

    // CSR per branch (dst-sorted, self-loops included)
    for (int b = 0; b < 2; b++) {
        k_fill_int<<<(NN + 255) / 256, 256>>>(CUR[b], 1, NN);
        k_hist<<<(EE + 255) / 256, 256>>>(EI[b] + EE, CUR[b], EE);
        k_scan<<<1, 1024>>>(CUR[b], PTR[b], NN);
        k_copy_int<<<(NN + 255) / 256, 256>>>(PTR[b], CUR[b], NN);
        k_scatter<<<(ENN + 255) / 256, 256>>>(EI[b], CUR[b], COL[b], EE, NN);
    }

    // transposed LSTM weights + combined biases
    for (int bd = 0; bd < 4; bd++) {
        k_transpose<<<(768 * 128 + 255) / 256, 256>>>(Wih + (size_t)bd * 768 * 128,
                                                      WIHT + (size_t)bd * 98304, 768, 128);
        k_transpose<<<(768 * 192 + 255) / 256, 256>>>(Whh + (size_t)bd * 768 * 192,
                                                      WHHT + (size_t)bd * 147456, 768, 192);
    }
    k_bsum<<<(3072 + 255) / 256, 256>>>(bih, bhh, BSUM, 3072);

    // GAT layers (split-tf32 GEMM: errors here compound across layers)
    const float* xcur[2] = { X0[0], X0[1] };
    for (int i = 0; i < 3; i++) {
        k_mean<<<(int)((SZ_NF + 255) / 256), 256>>>(xcur[0], xcur[1], MEAN, SZ_NF);
        for (int b = 0; b < 2; b++) {
            float* xs_out = fp + OFF_XS + ((size_t)b * 3 + i) * SZ_NF;
            gemm(xcur[b], conv_W + ((size_t)b * 3 + i) * 128 * 256, nullptr, XH,
                 NN, 256, 128, 0, 1);
            k_att<<<WB, 256>>>(XH, att_src + ((size_t)b * 3 + i) * 256,
                               att_dst + ((size_t)b * 3 + i) * 256, ASRC, ADST, NN);
            k_aggr<<<WB, 256>>>(PTR[b], COL[b], XH, ASRC, ADST,
                                conv_b + ((size_t)b * 3 + i) * 128, MEAN, xs_out, NN);
        }
        xcur[0] = fp + OFF_XS + (size_t)i * SZ_NF;
        xcur[1] = fp + OFF_XS + ((size_t)3 + i) * SZ_NF;
    }

    // JK bi-LSTM + layer attention, per branch (single-pass tf32: error damped)
    for (int b = 0; b < 2; b++) {
        for (int d = 0; d < 2; d++) {
            int bd = b * 2 + d;
            float* Hbuf = (d == 0) ? HF : HB;
            const float* hprev = nullptr;
            for (int step = 0; step < 3; step++) {
                int si = (d == 0) ? step : 2 - step;
                const float* xs = fp + OFF_XS + ((size_t)b * 3 + si) * SZ_NF;
                gemm(xs, WIHT + (size_t)bd * 98304, nullptr, G, NN, 768, 128, 0, 0);
                if (step > 0)
                    gemm(hprev, WHHT + (size_t)bd * 147456, nullptr, G, NN, 768, 192, 1, 0);
                float* hout = Hbuf + (size_t)si * NN * 192;
                k_lstm<<<(NN * 192 + 255) / 256, 256>>>(G, BSUM + (size_t)bd * 768,
                                                        (step == 0) ? nullptr : CST,
                                                        CST, hout, NN);
                hprev = hout;
            }
        }
        k_jk<<<WB, 256>>>(HF, HB, jkW + (size_t)b * 384,
                          fp + OFF_XS + ((size_t)b * 3 + 0) * SZ_NF,
                          fp + OFF_XS + ((size_t)b * 3 + 1) * SZ_NF,
                          fp + OFF_XS + ((size_t)b * 3 + 2) * SZ_NF, JK[b], NN);
    }

    // heads (split: feeds output directly)
    for (int b = 0; b < 2; b++)
        gemm(JK[b], dW + (size_t)b * 128 * 128, dB + (size_t)b * 128, SQ[b],
             NN, 128, 128, 0, 1);
    const float* feats[4] = { JK[0], SQ[0], JK[1], SQ[1] };
    for (int i = 0; i < 4; i++)
        gemm(feats[i], fW + (size_t)i * 128 * 128, fB + (size_t)i * 128,
             O4 + (size_t)i * SZ_NF, NN, 128, 128, 0, 1);

    k_final<<<WB, 256>>>(O4, lW, out, NN);
}